// round 12
// baseline (speedup 1.0000x reference)
#include <cuda_runtime.h>
#include <cuda_fp16.h>
#include <math.h>
#include <stdint.h>

#define Nn   50000
#define Ee   1600000
#define INf  64
#define HIDf 128
#define LATf 32
#define Hh   8
#define Ll   3
#define Gg   64
#define ET   (Ee + Nn)

#define NCH_E 8    // K chunks of 128 for embed  (K = 1024)
#define NCH_M 16   // K chunks of 128 for mp     (K = 2048)
#define CHUNK_ELEMS (128 * 128)   // weights per chunk (out x kc)

#define NTHREADS 384   // 8 consumer warps + 4 producer warps
#define TAILC    53    // tail CTAs fused into embed launch (wave-3 slack)

// ---------------- scratch (static device globals) ---------------------------
__device__ int    g_deg[Nn];
__device__ int    g_off[Nn + 1];
__device__ int    g_cur[Nn];
__device__ float  g_dinv[Nn];
__device__ int    g_crow[ET];
__device__ float  g_cnorm[ET];
__device__ float  g_h0[Nn * HIDf];          // embed out / aggregate ping
__device__ float  g_h1[Nn * HIDf];          // aggregate pong
__device__ __half g_hk[Nn * HIDf];          // mp kan out (pre-aggregation), fp16
__device__ __half g_WEh[NCH_E * CHUNK_ELEMS];   // [chunk][out 128][kc 128] hi
__device__ __half g_WEl[NCH_E * CHUNK_ELEMS];   // lo residual
__device__ __half g_WMh[Ll * NCH_M * CHUNK_ELEMS];
__device__ __half g_WMl[Ll * NCH_M * CHUNK_ELEMS];
__device__ float  g_pool[Gg * HIDf];
__device__ float  g_gcnt[Gg];

// ---------------- PTX helpers -----------------------------------------------
__device__ __forceinline__ uint32_t smem_u32(const void* p) {
    uint32_t a;
    asm("{ .reg .u64 t; cvta.to.shared.u64 t, %1; cvt.u32.u64 %0, t; }" : "=r"(a) : "l"(p));
    return a;
}
__device__ __forceinline__ void ldsm4(uint32_t* r, uint32_t a) {
    asm volatile("ldmatrix.sync.aligned.m8n8.x4.shared.b16 {%0,%1,%2,%3}, [%4];"
                 : "=r"(r[0]), "=r"(r[1]), "=r"(r[2]), "=r"(r[3]) : "r"(a));
}
__device__ __forceinline__ void mma_f16(float* d, const uint32_t* a, const uint32_t* b) {
    asm volatile(
        "mma.sync.aligned.m16n8k16.row.col.f32.f16.f16.f32 "
        "{%0,%1,%2,%3},{%4,%5,%6,%7},{%8,%9},{%0,%1,%2,%3};"
        : "+f"(d[0]), "+f"(d[1]), "+f"(d[2]), "+f"(d[3])
        : "r"(a[0]), "r"(a[1]), "r"(a[2]), "r"(a[3]), "r"(b[0]), "r"(b[1]));
}
__device__ __forceinline__ void cp16(uint32_t dst, const void* src) {
    asm volatile("cp.async.cg.shared.global [%0], [%1], 16;" :: "r"(dst), "l"(src));
}
__device__ __forceinline__ void cp_commit() {
    asm volatile("cp.async.commit_group;" ::: "memory");
}
template <int N>
__device__ __forceinline__ void cp_wait() {
    asm volatile("cp.async.wait_group %0;" :: "n"(N) : "memory");
}
__device__ __forceinline__ void bar_sync(int id) {
    asm volatile("bar.sync %0, %1;" :: "r"(id), "r"(NTHREADS) : "memory");
}
__device__ __forceinline__ void bar_arrive(int id) {
    asm volatile("bar.arrive %0, %1;" :: "r"(id), "r"(NTHREADS) : "memory");
}
__device__ __forceinline__ void membar_cta() {
    asm volatile("membar.cta;" ::: "memory");
}

// barrier ids: FULL(s) = 1+s, EMPTY(s) = 3+s
#define FULL_ID(s)  (1 + (s))
#define EMPTY_ID(s) (3 + (s))

// ---------------- weight reorg + scratch zero-init ---------------------------
// K order: k = i*16 + t*8 + h.  Dest: [chunk = k>>7][out][kc = k&127].
// Also zeroes g_deg / g_pool / g_gcnt for this call (no separate init launch).
#define EMB_ELEMS (INf * 16 * HIDf)    // 131072
#define MP_ELEMS  (HIDf * 16 * HIDf)   // 262144
__global__ void k_reorg(const float* __restrict__ We, const float* __restrict__ Wm) {
    int idx = blockIdx.x * blockDim.x + threadIdx.x;
    // fused zero-init (runs in the launch BEFORE any counting)
    if (idx < Nn) g_deg[idx] = 0;
    if (idx < Gg * HIDf) g_pool[idx] = 0.f;
    if (idx < Gg) g_gcnt[idx] = 0.f;

    int total = EMB_ELEMS + Ll * MP_ELEMS;
    if (idx >= total) return;
    const float* W;
    __half *Dh, *Dl;
    int INP, rem;
    if (idx < EMB_ELEMS) {
        W = We; Dh = g_WEh; Dl = g_WEl; INP = INf; rem = idx;
    } else {
        int t2 = idx - EMB_ELEMS;
        int l = t2 / MP_ELEMS;
        rem = t2 - l * MP_ELEMS;
        W = Wm + (size_t)l * 2 * HIDf * HIDf * Hh;
        Dh = g_WMh + (size_t)l * NCH_M * CHUNK_ELEMS;
        Dl = g_WMl + (size_t)l * NCH_M * CHUNK_ELEMS;
        INP = HIDf;
    }
    int o = rem & 127;
    int k = rem >> 7;
    int chunk = k >> 7, kc = k & 127;
    int i = k >> 4, t = (k >> 3) & 1, h = k & 7;
    float w = W[((t * HIDf + o) * INP + i) * Hh + h];
    __half hi = __float2half_rn(w);
    __half lo = __float2half_rn(w - __half2float(hi));
    int dst = (chunk * 128 + o) * 128 + kc;
    Dh[dst] = hi;
    Dl[dst] = lo;
}

// ---------------- scan: offsets (deg+1 for self loop) + dinv ------------------
__global__ void k_scan() {
    __shared__ int partial[1024];
    const int CH = (Nn + 1023) / 1024;
    int tid = threadIdx.x;
    int base = tid * CH;
    int sum = 0;
    for (int j = 0; j < CH; j++) { int i = base + j; if (i < Nn) sum += g_deg[i] + 1; }
    partial[tid] = sum;
    __syncthreads();
    if (tid == 0) {
        int run = 0;
        for (int i = 0; i < 1024; i++) { int t = partial[i]; partial[i] = run; run += t; }
        g_off[Nn] = run;
    }
    __syncthreads();
    int run = partial[tid];
    for (int j = 0; j < CH; j++) {
        int i = base + j;
        if (i < Nn) {
            int d = g_deg[i] + 1;            // +1 self loop
            g_off[i] = run; g_cur[i] = run;
            g_dinv[i] = rsqrtf((float)d);
            run += d;
        }
    }
}
__global__ void k_fill(const int* __restrict__ row, const int* __restrict__ col) {
    int idx = blockIdx.x * blockDim.x + threadIdx.x;
    if (idx >= ET) return;
    int r, c;
    if (idx < Ee) { r = row[idx]; c = col[idx]; }
    else          { r = c = idx - Ee; }
    int pos = atomicAdd(&g_cur[c], 1);
    g_crow[pos] = r;
    g_cnorm[pos] = g_dinv[r] * g_dinv[c];
}

// ---------------- KAN GEMM: warp-specialized, K-chunks of 128 ----------------
// CTA: 128 nodes x 128 outs, 384 threads. 8 consumer warps (64x32 each),
// 4 producer warps (trig A-fill + B cp.async). Double-buffered K=128 stages.
// Embed launch carries TAILC extra CTAs doing degree/batch counting in the
// wave-3 scheduling slack (391 = 148+148+95 -> 53 free SM slots).
#define A_STRIDE 136
#define ROW_B    (A_STRIDE * 2)              // 272 bytes
#define TILE_B   (128 * ROW_B)               // 34816 bytes
#define STAGE_B  (3 * TILE_B)                // A + Bh + Bl = 104448
#define A_OFF(s)  ((s) * STAGE_B)
#define BH_OFF(s) ((s) * STAGE_B + TILE_B)
#define BL_OFF(s) ((s) * STAGE_B + 2 * TILE_B)
#define SMEM_SZ  (2 * STAGE_B)               // 208896

template <int NCHUNK, typename OutT>
__global__ __launch_bounds__(NTHREADS, 1) void k_kan_mma(const float* __restrict__ X,
                                                         const __half* __restrict__ Wh,
                                                         const __half* __restrict__ Wl,
                                                         OutT* __restrict__ Y, int B,
                                                         int ntile,
                                                         const int* __restrict__ cnt_col,
                                                         const int* __restrict__ cnt_batch) {
    extern __shared__ char sm[];
    const int INP = NCHUNK * 8;
    int tid = threadIdx.x;

    if ((int)blockIdx.x >= ntile) {
        // ======= TAIL CTA: degree histogram + batch counts (embed only) =======
        int t = blockIdx.x - ntile;
        int nthr = (gridDim.x - ntile) * NTHREADS;
        for (int e = t * NTHREADS + tid; e < Ee; e += nthr)
            atomicAdd(&g_deg[cnt_col[e]], 1);
        for (int i = t * NTHREADS + tid; i < Nn; i += nthr)
            atomicAdd(&g_gcnt[cnt_batch[i]], 1.f);
        return;
    }

    uint32_t sb = smem_u32(sm);
    int lane = tid & 31;
    int wid = tid >> 5;
    int nb = blockIdx.x * 128;

    if (wid < 8) {
        // ====== CONSUMER: 64 m-rows x 32 n-cols per warp, MMA only ======
        int m0 = (wid & 1) * 64;
        int n0 = (wid >> 1) * 32;
        int koff = (wid >> 2) * 4;          // de-phase warp halves per SMSP

        float d[4][4][4];
#pragma unroll
        for (int a = 0; a < 4; a++)
#pragma unroll
            for (int b = 0; b < 4; b++)
#pragma unroll
                for (int q = 0; q < 4; q++) d[a][b][q] = 0.f;

        uint32_t arow = (uint32_t)(((lane >> 3) & 1) * 8 + (lane & 7));
        uint32_t brow = (uint32_t)((lane >> 4) * 8 + (lane & 7));

        uint32_t fa[2][4][4], fbh[2][2][4], fbl[2][2][4];

        auto load_frags = [&](int buf, int kk, int s) {
            int k0 = kk * 16;
            uint32_t acol = (uint32_t)(k0 + (lane >> 4) * 8);
#pragma unroll
            for (int mt = 0; mt < 4; mt++)
                ldsm4(fa[buf][mt],
                      sb + A_OFF(s) + (uint32_t)((m0 + mt * 16 + arow) * ROW_B) + acol * 2);
            uint32_t bcol = (uint32_t)(k0 + ((lane >> 3) & 1) * 8);
#pragma unroll
            for (int np = 0; np < 2; np++) {
                uint32_t off = (uint32_t)((n0 + np * 16 + brow) * ROW_B) + bcol * 2;
                ldsm4(fbh[buf][np], sb + BH_OFF(s) + off);
                ldsm4(fbl[buf][np], sb + BL_OFF(s) + off);
            }
        };

        for (int c = 0; c < NCHUNK; c++) {
            int s = c & 1;
            bar_sync(FULL_ID(s));           // wait stage s filled

            load_frags(0, koff, s);
#pragma unroll
            for (int j = 0; j < 8; j++) {
                int cur = j & 1;
                if (j < 7) load_frags(cur ^ 1, (koff + j + 1) & 7, s);
#pragma unroll
                for (int np = 0; np < 2; np++)
#pragma unroll
                    for (int mt = 0; mt < 4; mt++) {
                        mma_f16(d[mt][np * 2 + 0], fa[cur][mt], fbh[cur][np] + 0);
                        mma_f16(d[mt][np * 2 + 1], fa[cur][mt], fbh[cur][np] + 2);
                    }
#pragma unroll
                for (int np = 0; np < 2; np++)
#pragma unroll
                    for (int mt = 0; mt < 4; mt++) {
                        mma_f16(d[mt][np * 2 + 0], fa[cur][mt], fbl[cur][np] + 0);
                        mma_f16(d[mt][np * 2 + 1], fa[cur][mt], fbl[cur][np] + 2);
                    }
            }
            bar_arrive(EMPTY_ID(s));        // release stage s
        }

        // ---- epilogue (4 m-tiles x 4 n8-slabs)
#pragma unroll
        for (int mt = 0; mt < 4; mt++) {
#pragma unroll
            for (int nt = 0; nt < 4; nt++) {
                int row = nb + m0 + mt * 16 + (lane >> 2);
                int out = n0 + nt * 8 + (lane & 3) * 2;
                if constexpr (sizeof(OutT) == 2) {
                    if (row < B) {
                        *(__half2*)&Y[(size_t)row * HIDf + out] =
                            __floats2half2_rn(d[mt][nt][0], d[mt][nt][1]);
                    }
                    if (row + 8 < B) {
                        *(__half2*)&Y[(size_t)(row + 8) * HIDf + out] =
                            __floats2half2_rn(d[mt][nt][2], d[mt][nt][3]);
                    }
                } else {
                    if (row < B) {
                        float2 p; p.x = d[mt][nt][0]; p.y = d[mt][nt][1];
                        *(float2*)&Y[(size_t)row * HIDf + out] = p;
                    }
                    if (row + 8 < B) {
                        float2 p; p.x = d[mt][nt][2]; p.y = d[mt][nt][3];
                        *(float2*)&Y[(size_t)(row + 8) * HIDf + out] = p;
                    }
                }
            }
        }
    } else {
        // ================= PRODUCER: A trig fill + B cp.async =================
        int pt = tid - 256;                 // 0..127 (one node per thread)
        bool pvalid = (nb + pt) < B;
        const float* xrow = X + (size_t)(nb + pt) * INP;

        for (int c = 0; c < NCHUNK; c++) {
            int s = c & 1;
            if (c >= 2) bar_sync(EMPTY_ID(s));   // wait consumers freed stage

            // ---- B: cp.async hi + lo K=128 chunks into stage s
            {
                const char* srcH = (const char*)(Wh + (size_t)c * CHUNK_ELEMS);
                const char* srcL = (const char*)(Wl + (size_t)c * CHUNK_ELEMS);
#pragma unroll
                for (int j = 0; j < 16; j++) {
                    int idx = pt + 128 * j;
                    uint32_t dof = (uint32_t)((idx >> 4) * ROW_B + (idx & 15) * 16);
                    cp16(sb + BH_OFF(s) + dof, srcH + idx * 16);
                    cp16(sb + BL_OFF(s) + dof, srcL + idx * 16);
                }
                cp_commit();
            }

            // ---- A: trig features for inputs 8c..8c+7 of node pt
            {
                float xs[8];
                if (pvalid) {
                    float4 a = *(const float4*)(xrow + 8 * c);
                    float4 b = *(const float4*)(xrow + 8 * c + 4);
                    xs[0] = a.x; xs[1] = a.y; xs[2] = a.z; xs[3] = a.w;
                    xs[4] = b.x; xs[5] = b.y; xs[6] = b.z; xs[7] = b.w;
                } else {
#pragma unroll
                    for (int j = 0; j < 8; j++) xs[j] = 0.f;
                }
#pragma unroll
                for (int j = 0; j < 8; j++) {
                    float s1, c1;
                    __sincosf(xs[j], &s1, &c1);
                    float cv[8], sv[8];
                    cv[0] = c1; sv[0] = s1;
#pragma unroll
                    for (int h = 1; h < 8; h++) {
                        cv[h] = cv[h - 1] * c1 - sv[h - 1] * s1;
                        sv[h] = sv[h - 1] * c1 + cv[h - 1] * s1;
                    }
                    float v[16];
#pragma unroll
                    for (int h = 0; h < 8; h++) { v[h] = cv[h]; v[8 + h] = sv[h]; }
                    uint32_t base = (uint32_t)(pt * ROW_B + j * 32);
#pragma unroll
                    for (int q = 0; q < 8; q++) {
                        *(__half2*)(sm + A_OFF(s) + base + q * 4) =
                            __floats2half2_rn(v[2 * q], v[2 * q + 1]);
                    }
                }
            }

            cp_wait<0>();          // B for this chunk landed
            membar_cta();          // STS + cp.async visible CTA-wide
            bar_arrive(FULL_ID(s));
        }
    }
}

// ---------------- aggregation: warp per dest node, fp16 gather, fp32 out -----
__global__ void k_aggregate(const __half* __restrict__ hin, float* __restrict__ hout) {
    int warp = (blockIdx.x * blockDim.x + threadIdx.x) >> 5;
    int lane = threadIdx.x & 31;
    if (warp >= Nn) return;
    int s = g_off[warp];
    int e = g_off[warp + 1];
    float ax = 0.f, ay = 0.f, az = 0.f, aw = 0.f;
    int k = s;
    for (; k + 1 < e; k += 2) {
        int r0 = g_crow[k];     float n0 = g_cnorm[k];
        int r1 = g_crow[k + 1]; float n1 = g_cnorm[k + 1];
        const __half2* p0 = (const __half2*)(hin + (size_t)r0 * HIDf + lane * 4);
        const __half2* p1 = (const __half2*)(hin + (size_t)r1 * HIDf + lane * 4);
        float2 a0 = __half22float2(p0[0]), b0 = __half22float2(p0[1]);
        float2 a1 = __half22float2(p1[0]), b1 = __half22float2(p1[1]);
        ax += n0 * a0.x + n1 * a1.x;
        ay += n0 * a0.y + n1 * a1.y;
        az += n0 * b0.x + n1 * b1.x;
        aw += n0 * b0.y + n1 * b1.y;
    }
    if (k < e) {
        int r0 = g_crow[k]; float n0 = g_cnorm[k];
        const __half2* p0 = (const __half2*)(hin + (size_t)r0 * HIDf + lane * 4);
        float2 a0 = __half22float2(p0[0]), b0 = __half22float2(p0[1]);
        ax += n0 * a0.x; ay += n0 * a0.y; az += n0 * b0.x; aw += n0 * b0.y;
    }
    float4 o; o.x = ax; o.y = ay; o.z = az; o.w = aw;
    *(float4*)&hout[(size_t)warp * HIDf + lane * 4] = o;
}

// ---------------- pooling: segmented (batch sorted) ---------------------------
#define PNODES 32
__global__ void k_pool(const float* __restrict__ h, const int* __restrict__ batch) {
    __shared__ int sbatch[PNODES];
    int f = threadIdx.x;             // feature 0..127
    int n0 = blockIdx.x * PNODES;
    if (f < PNODES) {
        int n = n0 + f;
        sbatch[f] = (n < Nn) ? batch[n] : -1;
    }
    __syncthreads();
    float acc = 0.f;
    int curb = sbatch[0];
#pragma unroll 4
    for (int j = 0; j < PNODES; j++) {
        int n = n0 + j;
        if (n >= Nn) break;
        int b = sbatch[j];
        if (b != curb) {
            atomicAdd(&g_pool[curb * HIDf + f], acc);
            acc = 0.f; curb = b;
        }
        acc += h[(size_t)n * HIDf + f];
    }
    if (curb >= 0) atomicAdd(&g_pool[curb * HIDf + f], acc);
}

// ---------------- readout KAN: [G=64, 128] -> [G, 32] (mean-div inline) -------
__global__ void k_readout(const float* __restrict__ Wread, float* __restrict__ out) {
    __shared__ float trig[HIDf * 16];
    int g = blockIdx.x;
    int tid = threadIdx.x;
    {
        float cnt = fmaxf(g_gcnt[g], 1.f);
        float x = g_pool[g * HIDf + tid] / cnt;
        float s1, c1;
        __sincosf(x, &s1, &c1);
        float c = c1, s = s1;
#pragma unroll
        for (int h = 0; h < Hh; h++) {
            trig[tid * 16 + h] = c;
            trig[tid * 16 + 8 + h] = s;
            float c2 = c * c1 - s * s1;
            s = s * c1 + c * s1;
            c = c2;
        }
    }
    __syncthreads();
    if (tid < LATf) {
        int o = tid;
        float acc = 0.f;
        for (int i = 0; i < HIDf; i++) {
#pragma unroll
            for (int h = 0; h < Hh; h++) {
                acc += trig[i * 16 + h]     * Wread[((0 * LATf + o) * HIDf + i) * Hh + h];
                acc += trig[i * 16 + 8 + h] * Wread[((1 * LATf + o) * HIDf + i) * Hh + h];
            }
        }
        out[g * LATf + o] = acc;
    }
}

// ---------------- launch ------------------------------------------------------
extern "C" void kernel_launch(void* const* d_in, const int* in_sizes, int n_in,
                              void* d_out, int out_size) {
    const float* feat  = (const float*)d_in[0];
    const int*   eidx  = (const int*)d_in[1];
    const int*   batch = (const int*)d_in[2];
    const float* We    = (const float*)d_in[3];
    const float* Wm    = (const float*)d_in[4];
    const float* Wread = (const float*)d_in[5];
    float* out = (float*)d_out;

    const int* row = eidx;
    const int* col = eidx + Ee;

    float *h0, *h1;
    __half *hk, *weh, *wel, *wmh, *wml;
    cudaGetSymbolAddress((void**)&h0,  g_h0);
    cudaGetSymbolAddress((void**)&h1,  g_h1);
    cudaGetSymbolAddress((void**)&hk,  g_hk);
    cudaGetSymbolAddress((void**)&weh, g_WEh);
    cudaGetSymbolAddress((void**)&wel, g_WEl);
    cudaGetSymbolAddress((void**)&wmh, g_WMh);
    cudaGetSymbolAddress((void**)&wml, g_WMl);

    cudaFuncSetAttribute(k_kan_mma<NCH_E, float>,
                         cudaFuncAttributeMaxDynamicSharedMemorySize, SMEM_SZ);
    cudaFuncSetAttribute(k_kan_mma<NCH_M, __half>,
                         cudaFuncAttributeMaxDynamicSharedMemorySize, SMEM_SZ);

    const int NTILE = (Nn + 127) / 128;   // 391

    // reorg (+ zero-init of deg/pool/gcnt fused in)
    k_reorg<<<(EMB_ELEMS + Ll * MP_ELEMS + 255) / 256, 256>>>(We, Wm);

    // embed GEMM with TAILC counting CTAs hidden in wave-3 slack
    k_kan_mma<NCH_E, float><<<NTILE + TAILC, NTHREADS, SMEM_SZ>>>(
        feat, weh, wel, h0, Nn, NTILE, col, batch);

    // graph structure (scan adds +1 self loop; fill places edges + loops)
    k_scan<<<1, 1024>>>();
    k_fill<<<(ET + 255) / 256, 256>>>(row, col);

    // message passing layers (fp16 intermediate, fp32 aggregate output)
    const float* cur = h0;
    float* ping[2] = { h1, h0 };
    for (int l = 0; l < Ll; l++) {
        k_kan_mma<NCH_M, __half><<<NTILE, NTHREADS, SMEM_SZ>>>(
            cur, wmh + (size_t)l * NCH_M * CHUNK_ELEMS,
            wml + (size_t)l * NCH_M * CHUNK_ELEMS, hk, Nn,
            NTILE, (const int*)0, (const int*)0);
        float* dst = ping[l & 1];
        k_aggregate<<<(Nn * 32 + 255) / 256, 256>>>(hk, dst);
        cur = dst;
    }

    // pool + readout (mean divide fused into readout)
    k_pool<<<(Nn + PNODES - 1) / PNODES, HIDf>>>(cur, batch);
    k_readout<<<Gg, HIDf>>>(Wread, out);
}

// round 14
// speedup vs baseline: 1.0806x; 1.0806x over previous
#include <cuda_runtime.h>
#include <cuda_fp16.h>
#include <math.h>
#include <stdint.h>

#define Nn   50000
#define Ee   1600000
#define INf  64
#define HIDf 128
#define LATf 32
#define Hh   8
#define Ll   3
#define Gg   64
#define ET   (Ee + Nn)

#define NCH_E 8    // K chunks of 128 for embed  (K = 1024)
#define NCH_M 16   // K chunks of 128 for mp     (K = 2048)
#define CHUNK_ELEMS (128 * 128)   // weights per chunk (out x kc)

#define NTHREADS 384   // 8 consumer warps + 4 producer warps

// ---------------- scratch (static device globals) ---------------------------
__device__ int    g_deg[Nn];
__device__ int    g_off[Nn + 1];
__device__ int    g_cur[Nn];
__device__ float  g_dinv[Nn];
__device__ int2   g_edge[ET];               // (src row, norm bits) AoS
__device__ float  g_h0[Nn * HIDf];          // embed out / aggregate ping
__device__ float  g_h1[Nn * HIDf];          // aggregate pong
__device__ __half g_hk[Nn * HIDf];          // mp kan out (pre-aggregation), fp16
__device__ __half g_WEh[NCH_E * CHUNK_ELEMS];   // [chunk][out 128][kc 128] hi
__device__ __half g_WEl[NCH_E * CHUNK_ELEMS];   // lo residual
__device__ __half g_WMh[Ll * NCH_M * CHUNK_ELEMS];
__device__ __half g_WMl[Ll * NCH_M * CHUNK_ELEMS];
__device__ float  g_pool[Gg * HIDf];
__device__ float  g_gcnt[Gg];

// ---------------- PTX helpers -----------------------------------------------
__device__ __forceinline__ uint32_t smem_u32(const void* p) {
    uint32_t a;
    asm("{ .reg .u64 t; cvta.to.shared.u64 t, %1; cvt.u32.u64 %0, t; }" : "=r"(a) : "l"(p));
    return a;
}
__device__ __forceinline__ void ldsm4(uint32_t* r, uint32_t a) {
    asm volatile("ldmatrix.sync.aligned.m8n8.x4.shared.b16 {%0,%1,%2,%3}, [%4];"
                 : "=r"(r[0]), "=r"(r[1]), "=r"(r[2]), "=r"(r[3]) : "r"(a));
}
__device__ __forceinline__ void mma_f16(float* d, const uint32_t* a, const uint32_t* b) {
    asm volatile(
        "mma.sync.aligned.m16n8k16.row.col.f32.f16.f16.f32 "
        "{%0,%1,%2,%3},{%4,%5,%6,%7},{%8,%9},{%0,%1,%2,%3};"
        : "+f"(d[0]), "+f"(d[1]), "+f"(d[2]), "+f"(d[3])
        : "r"(a[0]), "r"(a[1]), "r"(a[2]), "r"(a[3]), "r"(b[0]), "r"(b[1]));
}
__device__ __forceinline__ void cp16(uint32_t dst, const void* src) {
    asm volatile("cp.async.cg.shared.global [%0], [%1], 16;" :: "r"(dst), "l"(src));
}
__device__ __forceinline__ void cp_commit() {
    asm volatile("cp.async.commit_group;" ::: "memory");
}
template <int N>
__device__ __forceinline__ void cp_wait() {
    asm volatile("cp.async.wait_group %0;" :: "n"(N) : "memory");
}
__device__ __forceinline__ void bar_sync(int id) {
    asm volatile("bar.sync %0, %1;" :: "r"(id), "r"(NTHREADS) : "memory");
}
__device__ __forceinline__ void bar_arrive(int id) {
    asm volatile("bar.arrive %0, %1;" :: "r"(id), "r"(NTHREADS) : "memory");
}
__device__ __forceinline__ void membar_cta() {
    asm volatile("membar.cta;" ::: "memory");
}

// barrier ids: FULL(s) = 1+s, EMPTY(s) = 3+s
#define FULL_ID(s)  (1 + (s))
#define EMPTY_ID(s) (3 + (s))

// ---------------- weight reorg + scratch zero-init ---------------------------
// K order: k = i*16 + t*8 + h.  Dest: [chunk = k>>7][out][kc = k&127].
#define EMB_ELEMS (INf * 16 * HIDf)    // 131072
#define MP_ELEMS  (HIDf * 16 * HIDf)   // 262144
__global__ void k_reorg(const float* __restrict__ We, const float* __restrict__ Wm) {
    int idx = blockIdx.x * blockDim.x + threadIdx.x;
    if (idx < Nn) g_deg[idx] = 0;            // fused zero-init
    if (idx < Gg * HIDf) g_pool[idx] = 0.f;

    int total = EMB_ELEMS + Ll * MP_ELEMS;
    if (idx >= total) return;
    const float* W;
    __half *Dh, *Dl;
    int INP, rem;
    if (idx < EMB_ELEMS) {
        W = We; Dh = g_WEh; Dl = g_WEl; INP = INf; rem = idx;
    } else {
        int t2 = idx - EMB_ELEMS;
        int l = t2 / MP_ELEMS;
        rem = t2 - l * MP_ELEMS;
        W = Wm + (size_t)l * 2 * HIDf * HIDf * Hh;
        Dh = g_WMh + (size_t)l * NCH_M * CHUNK_ELEMS;
        Dl = g_WMl + (size_t)l * NCH_M * CHUNK_ELEMS;
        INP = HIDf;
    }
    int o = rem & 127;
    int k = rem >> 7;
    int chunk = k >> 7, kc = k & 127;
    int i = k >> 4, t = (k >> 3) & 1, h = k & 7;
    float w = W[((t * HIDf + o) * INP + i) * Hh + h];
    __half hi = __float2half_rn(w);
    __half lo = __float2half_rn(w - __half2float(hi));
    int dst = (chunk * 128 + o) * 128 + kc;
    Dh[dst] = hi;
    Dl[dst] = lo;
}

// ---------------- degree count ------------------------------------------------
__global__ void k_count(const int* __restrict__ col) {
    int e = blockIdx.x * blockDim.x + threadIdx.x;
    if (e < Ee) atomicAdd(&g_deg[col[e]], 1);
}

// ---------------- scan: offsets (deg+1 self loop) + dinv + batch histogram ----
__global__ void k_scan(const int* __restrict__ batch) {
    __shared__ int partial[1024];
    __shared__ int hist[Gg];
    const int CH = (Nn + 1023) / 1024;
    int tid = threadIdx.x;
    if (tid < Gg) hist[tid] = 0;
    int base = tid * CH;
    int sum = 0;
    for (int j = 0; j < CH; j++) { int i = base + j; if (i < Nn) sum += g_deg[i] + 1; }
    partial[tid] = sum;
    __syncthreads();
    // batch histogram (sorted batch -> low shared-atomic contention is fine)
    for (int i = tid; i < Nn; i += 1024) atomicAdd(&hist[batch[i]], 1);
    if (tid == 0) {
        int run = 0;
        for (int i = 0; i < 1024; i++) { int t = partial[i]; partial[i] = run; run += t; }
        g_off[Nn] = run;
    }
    __syncthreads();
    if (tid < Gg) g_gcnt[tid] = (float)hist[tid];
    int run = partial[tid];
    for (int j = 0; j < CH; j++) {
        int i = base + j;
        if (i < Nn) {
            int d = g_deg[i] + 1;            // +1 self loop
            g_off[i] = run; g_cur[i] = run;
            g_dinv[i] = rsqrtf((float)d);
            run += d;
        }
    }
}

// ---------------- fill CSC: combined (row, norm) AoS record -------------------
__global__ void k_fill(const int* __restrict__ row, const int* __restrict__ col) {
    int idx = blockIdx.x * blockDim.x + threadIdx.x;
    if (idx >= ET) return;
    int r, c;
    if (idx < Ee) { r = row[idx]; c = col[idx]; }
    else          { r = c = idx - Ee; }
    int pos = atomicAdd(&g_cur[c], 1);
    int2 rec;
    rec.x = r;
    rec.y = __float_as_int(g_dinv[r] * g_dinv[c]);
    g_edge[pos] = rec;
}

// ---------------- KAN GEMM: warp-specialized, K-chunks of 128 ----------------
// CTA: 128 nodes x 128 outs, 384 threads. 8 consumer warps (64x32 each),
// 4 producer warps (trig A-fill + B cp.async). Double-buffered K=128 stages.
#define A_STRIDE 136
#define ROW_B    (A_STRIDE * 2)              // 272 bytes
#define TILE_B   (128 * ROW_B)               // 34816 bytes
#define STAGE_B  (3 * TILE_B)                // A + Bh + Bl = 104448
#define A_OFF(s)  ((s) * STAGE_B)
#define BH_OFF(s) ((s) * STAGE_B + TILE_B)
#define BL_OFF(s) ((s) * STAGE_B + 2 * TILE_B)
#define SMEM_SZ  (2 * STAGE_B)               // 208896

template <int NCHUNK, typename OutT>
__global__ __launch_bounds__(NTHREADS, 1) void k_kan_mma(const float* __restrict__ X,
                                                         const __half* __restrict__ Wh,
                                                         const __half* __restrict__ Wl,
                                                         OutT* __restrict__ Y, int B) {
    extern __shared__ char sm[];
    const int INP = NCHUNK * 8;
    uint32_t sb = smem_u32(sm);
    int tid = threadIdx.x;
    int lane = tid & 31;
    int wid = tid >> 5;
    int nb = blockIdx.x * 128;

    if (wid < 8) {
        // ====== CONSUMER: 64 m-rows x 32 n-cols per warp, MMA only ======
        int m0 = (wid & 1) * 64;
        int n0 = (wid >> 1) * 32;
        int koff = (wid >> 2) * 4;          // de-phase warp halves per SMSP

        float d[4][4][4];
#pragma unroll
        for (int a = 0; a < 4; a++)
#pragma unroll
            for (int b = 0; b < 4; b++)
#pragma unroll
                for (int q = 0; q < 4; q++) d[a][b][q] = 0.f;

        uint32_t arow = (uint32_t)(((lane >> 3) & 1) * 8 + (lane & 7));
        uint32_t brow = (uint32_t)((lane >> 4) * 8 + (lane & 7));

        uint32_t fa[2][4][4], fbh[2][2][4], fbl[2][2][4];

        auto load_frags = [&](int buf, int kk, int s) {
            int k0 = kk * 16;
            uint32_t acol = (uint32_t)(k0 + (lane >> 4) * 8);
#pragma unroll
            for (int mt = 0; mt < 4; mt++)
                ldsm4(fa[buf][mt],
                      sb + A_OFF(s) + (uint32_t)((m0 + mt * 16 + arow) * ROW_B) + acol * 2);
            uint32_t bcol = (uint32_t)(k0 + ((lane >> 3) & 1) * 8);
#pragma unroll
            for (int np = 0; np < 2; np++) {
                uint32_t off = (uint32_t)((n0 + np * 16 + brow) * ROW_B) + bcol * 2;
                ldsm4(fbh[buf][np], sb + BH_OFF(s) + off);
                ldsm4(fbl[buf][np], sb + BL_OFF(s) + off);
            }
        };

        for (int c = 0; c < NCHUNK; c++) {
            int s = c & 1;
            bar_sync(FULL_ID(s));           // wait stage s filled

            load_frags(0, koff, s);
#pragma unroll
            for (int j = 0; j < 8; j++) {
                int cur = j & 1;
                if (j < 7) load_frags(cur ^ 1, (koff + j + 1) & 7, s);
#pragma unroll
                for (int np = 0; np < 2; np++)
#pragma unroll
                    for (int mt = 0; mt < 4; mt++) {
                        mma_f16(d[mt][np * 2 + 0], fa[cur][mt], fbh[cur][np] + 0);
                        mma_f16(d[mt][np * 2 + 1], fa[cur][mt], fbh[cur][np] + 2);
                    }
#pragma unroll
                for (int np = 0; np < 2; np++)
#pragma unroll
                    for (int mt = 0; mt < 4; mt++) {
                        mma_f16(d[mt][np * 2 + 0], fa[cur][mt], fbl[cur][np] + 0);
                        mma_f16(d[mt][np * 2 + 1], fa[cur][mt], fbl[cur][np] + 2);
                    }
            }
            bar_arrive(EMPTY_ID(s));        // release stage s
        }

        // ---- epilogue (4 m-tiles x 4 n8-slabs)
#pragma unroll
        for (int mt = 0; mt < 4; mt++) {
#pragma unroll
            for (int nt = 0; nt < 4; nt++) {
                int row = nb + m0 + mt * 16 + (lane >> 2);
                int out = n0 + nt * 8 + (lane & 3) * 2;
                if constexpr (sizeof(OutT) == 2) {
                    if (row < B) {
                        *(__half2*)&Y[(size_t)row * HIDf + out] =
                            __floats2half2_rn(d[mt][nt][0], d[mt][nt][1]);
                    }
                    if (row + 8 < B) {
                        *(__half2*)&Y[(size_t)(row + 8) * HIDf + out] =
                            __floats2half2_rn(d[mt][nt][2], d[mt][nt][3]);
                    }
                } else {
                    if (row < B) {
                        float2 p; p.x = d[mt][nt][0]; p.y = d[mt][nt][1];
                        *(float2*)&Y[(size_t)row * HIDf + out] = p;
                    }
                    if (row + 8 < B) {
                        float2 p; p.x = d[mt][nt][2]; p.y = d[mt][nt][3];
                        *(float2*)&Y[(size_t)(row + 8) * HIDf + out] = p;
                    }
                }
            }
        }
    } else {
        // ================= PRODUCER: A trig fill + B cp.async =================
        int pt = tid - 256;                 // 0..127 (one node per thread)
        bool pvalid = (nb + pt) < B;
        const float* xrow = X + (size_t)(nb + pt) * INP;

        for (int c = 0; c < NCHUNK; c++) {
            int s = c & 1;
            if (c >= 2) bar_sync(EMPTY_ID(s));   // wait consumers freed stage

            // ---- B: cp.async hi + lo K=128 chunks into stage s
            {
                const char* srcH = (const char*)(Wh + (size_t)c * CHUNK_ELEMS);
                const char* srcL = (const char*)(Wl + (size_t)c * CHUNK_ELEMS);
#pragma unroll
                for (int j = 0; j < 16; j++) {
                    int idx = pt + 128 * j;
                    uint32_t dof = (uint32_t)((idx >> 4) * ROW_B + (idx & 15) * 16);
                    cp16(sb + BH_OFF(s) + dof, srcH + idx * 16);
                    cp16(sb + BL_OFF(s) + dof, srcL + idx * 16);
                }
                cp_commit();
            }

            // ---- A: trig features for inputs 8c..8c+7 of node pt
            {
                float xs[8];
                if (pvalid) {
                    float4 a = *(const float4*)(xrow + 8 * c);
                    float4 b = *(const float4*)(xrow + 8 * c + 4);
                    xs[0] = a.x; xs[1] = a.y; xs[2] = a.z; xs[3] = a.w;
                    xs[4] = b.x; xs[5] = b.y; xs[6] = b.z; xs[7] = b.w;
                } else {
#pragma unroll
                    for (int j = 0; j < 8; j++) xs[j] = 0.f;
                }
#pragma unroll
                for (int j = 0; j < 8; j++) {
                    float s1, c1;
                    __sincosf(xs[j], &s1, &c1);
                    float cv[8], sv[8];
                    cv[0] = c1; sv[0] = s1;
#pragma unroll
                    for (int h = 1; h < 8; h++) {
                        cv[h] = cv[h - 1] * c1 - sv[h - 1] * s1;
                        sv[h] = sv[h - 1] * c1 + cv[h - 1] * s1;
                    }
                    float v[16];
#pragma unroll
                    for (int h = 0; h < 8; h++) { v[h] = cv[h]; v[8 + h] = sv[h]; }
                    uint32_t base = (uint32_t)(pt * ROW_B + j * 32);
#pragma unroll
                    for (int q = 0; q < 8; q++) {
                        *(__half2*)(sm + A_OFF(s) + base + q * 4) =
                            __floats2half2_rn(v[2 * q], v[2 * q + 1]);
                    }
                }
            }

            cp_wait<0>();          // B for this chunk landed
            membar_cta();          // STS + cp.async visible CTA-wide
            bar_arrive(FULL_ID(s));
        }
    }
}

// ---------------- aggregation: warp per dest node, AoS edges, fp16 gather ----
__global__ void k_aggregate(const __half* __restrict__ hin, float* __restrict__ hout) {
    int warp = (blockIdx.x * blockDim.x + threadIdx.x) >> 5;
    int lane = threadIdx.x & 31;
    if (warp >= Nn) return;
    int s = g_off[warp];
    int e = g_off[warp + 1];
    float ax = 0.f, ay = 0.f, az = 0.f, aw = 0.f;
    int k = s;
    for (; k + 1 < e; k += 2) {
        int2 e0 = g_edge[k];
        int2 e1 = g_edge[k + 1];
        float n0 = __int_as_float(e0.y);
        float n1 = __int_as_float(e1.y);
        const __half2* p0 = (const __half2*)(hin + (size_t)e0.x * HIDf + lane * 4);
        const __half2* p1 = (const __half2*)(hin + (size_t)e1.x * HIDf + lane * 4);
        float2 a0 = __half22float2(p0[0]), b0 = __half22float2(p0[1]);
        float2 a1 = __half22float2(p1[0]), b1 = __half22float2(p1[1]);
        ax += n0 * a0.x + n1 * a1.x;
        ay += n0 * a0.y + n1 * a1.y;
        az += n0 * b0.x + n1 * b1.x;
        aw += n0 * b0.y + n1 * b1.y;
    }
    if (k < e) {
        int2 e0 = g_edge[k];
        float n0 = __int_as_float(e0.y);
        const __half2* p0 = (const __half2*)(hin + (size_t)e0.x * HIDf + lane * 4);
        float2 a0 = __half22float2(p0[0]), b0 = __half22float2(p0[1]);
        ax += n0 * a0.x; ay += n0 * a0.y; az += n0 * b0.x; aw += n0 * b0.y;
    }
    float4 o; o.x = ax; o.y = ay; o.z = az; o.w = aw;
    *(float4*)&hout[(size_t)warp * HIDf + lane * 4] = o;
}

// ---------------- pooling: segmented (batch sorted) ---------------------------
#define PNODES 32
__global__ void k_pool(const float* __restrict__ h, const int* __restrict__ batch) {
    __shared__ int sbatch[PNODES];
    int f = threadIdx.x;             // feature 0..127
    int n0 = blockIdx.x * PNODES;
    if (f < PNODES) {
        int n = n0 + f;
        sbatch[f] = (n < Nn) ? batch[n] : -1;
    }
    __syncthreads();
    float acc = 0.f;
    int curb = sbatch[0];
#pragma unroll 4
    for (int j = 0; j < PNODES; j++) {
        int n = n0 + j;
        if (n >= Nn) break;
        int b = sbatch[j];
        if (b != curb) {
            atomicAdd(&g_pool[curb * HIDf + f], acc);
            acc = 0.f; curb = b;
        }
        acc += h[(size_t)n * HIDf + f];
    }
    if (curb >= 0) atomicAdd(&g_pool[curb * HIDf + f], acc);
}

// ---------------- readout KAN: [G=64, 128] -> [G, 32] (mean-div inline) -------
__global__ void k_readout(const float* __restrict__ Wread, float* __restrict__ out) {
    __shared__ float trig[HIDf * 16];
    int g = blockIdx.x;
    int tid = threadIdx.x;
    {
        float cnt = fmaxf(g_gcnt[g], 1.f);
        float x = g_pool[g * HIDf + tid] / cnt;
        float s1, c1;
        __sincosf(x, &s1, &c1);
        float c = c1, s = s1;
#pragma unroll
        for (int h = 0; h < Hh; h++) {
            trig[tid * 16 + h] = c;
            trig[tid * 16 + 8 + h] = s;
            float c2 = c * c1 - s * s1;
            s = s * c1 + c * s1;
            c = c2;
        }
    }
    __syncthreads();
    if (tid < LATf) {
        int o = tid;
        float acc = 0.f;
        for (int i = 0; i < HIDf; i++) {
#pragma unroll
            for (int h = 0; h < Hh; h++) {
                acc += trig[i * 16 + h]     * Wread[((0 * LATf + o) * HIDf + i) * Hh + h];
                acc += trig[i * 16 + 8 + h] * Wread[((1 * LATf + o) * HIDf + i) * Hh + h];
            }
        }
        out[g * LATf + o] = acc;
    }
}

// ---------------- launch ------------------------------------------------------
extern "C" void kernel_launch(void* const* d_in, const int* in_sizes, int n_in,
                              void* d_out, int out_size) {
    const float* feat  = (const float*)d_in[0];
    const int*   eidx  = (const int*)d_in[1];
    const int*   batch = (const int*)d_in[2];
    const float* We    = (const float*)d_in[3];
    const float* Wm    = (const float*)d_in[4];
    const float* Wread = (const float*)d_in[5];
    float* out = (float*)d_out;

    const int* row = eidx;
    const int* col = eidx + Ee;

    float *h0, *h1;
    __half *hk, *weh, *wel, *wmh, *wml;
    cudaGetSymbolAddress((void**)&h0,  g_h0);
    cudaGetSymbolAddress((void**)&h1,  g_h1);
    cudaGetSymbolAddress((void**)&hk,  g_hk);
    cudaGetSymbolAddress((void**)&weh, g_WEh);
    cudaGetSymbolAddress((void**)&wel, g_WEl);
    cudaGetSymbolAddress((void**)&wmh, g_WMh);
    cudaGetSymbolAddress((void**)&wml, g_WMl);

    cudaFuncSetAttribute(k_kan_mma<NCH_E, float>,
                         cudaFuncAttributeMaxDynamicSharedMemorySize, SMEM_SZ);
    cudaFuncSetAttribute(k_kan_mma<NCH_M, __half>,
                         cudaFuncAttributeMaxDynamicSharedMemorySize, SMEM_SZ);

    const int NTILE = (Nn + 127) / 128;   // 391

    // reorg (+ zero-init of deg/pool fused in), then degree count
    k_reorg<<<(EMB_ELEMS + Ll * MP_ELEMS + 255) / 256, 256>>>(We, Wm);
    k_count<<<(Ee + 255) / 256, 256>>>(col);

    // embed (fp32 output: consumed directly as next kan input)
    k_kan_mma<NCH_E, float><<<NTILE, NTHREADS, SMEM_SZ>>>(feat, weh, wel, h0, Nn);

    // graph structure (scan: offsets + dinv + batch histogram; fill: AoS edges)
    k_scan<<<1, 1024>>>(batch);
    k_fill<<<(ET + 255) / 256, 256>>>(row, col);

    // message passing layers (fp16 intermediate, fp32 aggregate output)
    const float* cur = h0;
    float* ping[2] = { h1, h0 };
    for (int l = 0; l < Ll; l++) {
        k_kan_mma<NCH_M, __half><<<NTILE, NTHREADS, SMEM_SZ>>>(
            cur, wmh + (size_t)l * NCH_M * CHUNK_ELEMS,
            wml + (size_t)l * NCH_M * CHUNK_ELEMS, hk, Nn);
        float* dst = ping[l & 1];
        k_aggregate<<<(Nn * 32 + 255) / 256, 256>>>(hk, dst);
        cur = dst;
    }

    // pool + readout (mean divide fused into readout)
    k_pool<<<(Nn + PNODES - 1) / PNODES, HIDf>>>(cur, batch);
    k_readout<<<Gg, HIDf>>>(Wread, out);
}

// round 15
// speedup vs baseline: 1.2314x; 1.1395x over previous
#include <cuda_runtime.h>
#include <cuda_fp16.h>
#include <math.h>
#include <stdint.h>

#define Nn   50000
#define Ee   1600000
#define INf  64
#define HIDf 128
#define LATf 32
#define Hh   8
#define Ll   3
#define Gg   64
#define ET   (Ee + Nn)

#define NCH_E 8    // K chunks of 128 for embed  (K = 1024)
#define NCH_M 16   // K chunks of 128 for mp     (K = 2048)
#define CHUNK_ELEMS (128 * 128)   // weights per chunk (out x kc)

#define NTHREADS 384   // 8 consumer warps + 4 producer warps
#define NSB 49         // scan blocks: ceil(50000 / 1024)

// ---------------- scratch (static device globals) ---------------------------
__device__ int    g_deg[Nn];
__device__ int    g_off[Nn + 1];
__device__ int    g_cur[Nn];
__device__ float  g_dinv[Nn];
__device__ int    g_bsum[NSB];
__device__ int2   g_edge[ET];               // (src row, norm bits) AoS
__device__ float  g_h0[Nn * HIDf];          // embed out / aggregate ping
__device__ float  g_h1[Nn * HIDf];          // aggregate pong
__device__ __half g_hk[Nn * HIDf];          // mp kan out (pre-aggregation), fp16
__device__ __half g_WEh[NCH_E * CHUNK_ELEMS];   // [chunk][out 128][kc 128] hi
__device__ __half g_WEl[NCH_E * CHUNK_ELEMS];   // lo residual
__device__ __half g_WMh[Ll * NCH_M * CHUNK_ELEMS];
__device__ __half g_WMl[Ll * NCH_M * CHUNK_ELEMS];
__device__ float  g_pool[Gg * HIDf];
__device__ float  g_gcnt[Gg];

// ---------------- PTX helpers -----------------------------------------------
__device__ __forceinline__ uint32_t smem_u32(const void* p) {
    uint32_t a;
    asm("{ .reg .u64 t; cvta.to.shared.u64 t, %1; cvt.u32.u64 %0, t; }" : "=r"(a) : "l"(p));
    return a;
}
__device__ __forceinline__ void ldsm4(uint32_t* r, uint32_t a) {
    asm volatile("ldmatrix.sync.aligned.m8n8.x4.shared.b16 {%0,%1,%2,%3}, [%4];"
                 : "=r"(r[0]), "=r"(r[1]), "=r"(r[2]), "=r"(r[3]) : "r"(a));
}
__device__ __forceinline__ void mma_f16(float* d, const uint32_t* a, const uint32_t* b) {
    asm volatile(
        "mma.sync.aligned.m16n8k16.row.col.f32.f16.f16.f32 "
        "{%0,%1,%2,%3},{%4,%5,%6,%7},{%8,%9},{%0,%1,%2,%3};"
        : "+f"(d[0]), "+f"(d[1]), "+f"(d[2]), "+f"(d[3])
        : "r"(a[0]), "r"(a[1]), "r"(a[2]), "r"(a[3]), "r"(b[0]), "r"(b[1]));
}
__device__ __forceinline__ void cp16(uint32_t dst, const void* src) {
    asm volatile("cp.async.cg.shared.global [%0], [%1], 16;" :: "r"(dst), "l"(src));
}
__device__ __forceinline__ void cp_commit() {
    asm volatile("cp.async.commit_group;" ::: "memory");
}
template <int N>
__device__ __forceinline__ void cp_wait() {
    asm volatile("cp.async.wait_group %0;" :: "n"(N) : "memory");
}
__device__ __forceinline__ void bar_sync(int id) {
    asm volatile("bar.sync %0, %1;" :: "r"(id), "r"(NTHREADS) : "memory");
}
__device__ __forceinline__ void bar_arrive(int id) {
    asm volatile("bar.arrive %0, %1;" :: "r"(id), "r"(NTHREADS) : "memory");
}
__device__ __forceinline__ void membar_cta() {
    asm volatile("membar.cta;" ::: "memory");
}

// barrier ids: FULL(s) = 1+s, EMPTY(s) = 3+s
#define FULL_ID(s)  (1 + (s))
#define EMPTY_ID(s) (3 + (s))

// ---------------- weight reorg + scratch zero-init ---------------------------
// K order: k = i*16 + t*8 + h.  Dest: [chunk = k>>7][out][kc = k&127].
#define EMB_ELEMS (INf * 16 * HIDf)    // 131072
#define MP_ELEMS  (HIDf * 16 * HIDf)   // 262144
__global__ void k_reorg(const float* __restrict__ We, const float* __restrict__ Wm) {
    int idx = blockIdx.x * blockDim.x + threadIdx.x;
    if (idx < Nn) g_deg[idx] = 0;            // fused zero-init
    if (idx < Gg * HIDf) g_pool[idx] = 0.f;
    if (idx < Gg) g_gcnt[idx] = 0.f;

    int total = EMB_ELEMS + Ll * MP_ELEMS;
    if (idx >= total) return;
    const float* W;
    __half *Dh, *Dl;
    int INP, rem;
    if (idx < EMB_ELEMS) {
        W = We; Dh = g_WEh; Dl = g_WEl; INP = INf; rem = idx;
    } else {
        int t2 = idx - EMB_ELEMS;
        int l = t2 / MP_ELEMS;
        rem = t2 - l * MP_ELEMS;
        W = Wm + (size_t)l * 2 * HIDf * HIDf * Hh;
        Dh = g_WMh + (size_t)l * NCH_M * CHUNK_ELEMS;
        Dl = g_WMl + (size_t)l * NCH_M * CHUNK_ELEMS;
        INP = HIDf;
    }
    int o = rem & 127;
    int k = rem >> 7;
    int chunk = k >> 7, kc = k & 127;
    int i = k >> 4, t = (k >> 3) & 1, h = k & 7;
    float w = W[((t * HIDf + o) * INP + i) * Hh + h];
    __half hi = __float2half_rn(w);
    __half lo = __float2half_rn(w - __half2float(hi));
    int dst = (chunk * 128 + o) * 128 + kc;
    Dh[dst] = hi;
    Dl[dst] = lo;
}

// ---------------- degree count ------------------------------------------------
__global__ void k_count(const int* __restrict__ col) {
    int e = blockIdx.x * blockDim.x + threadIdx.x;
    if (e < Ee) atomicAdd(&g_deg[col[e]], 1);
}

// ---------------- scan phase 1: per-block sums + batch histogram --------------
__global__ void k_scan1(const int* __restrict__ batch) {
    __shared__ int wsum[32];
    __shared__ int hist[Gg];
    int tid = threadIdx.x;
    if (tid < Gg) hist[tid] = 0;
    __syncthreads();
    int i = blockIdx.x * 1024 + tid;
    int d = (i < Nn) ? g_deg[i] + 1 : 0;     // +1 self loop
    if (i < Nn) atomicAdd(&hist[batch[i]], 1);
    int v = d;
#pragma unroll
    for (int o = 16; o > 0; o >>= 1) v += __shfl_down_sync(~0u, v, o);
    if ((tid & 31) == 0) wsum[tid >> 5] = v;
    __syncthreads();
    if (tid < 32) {
        int w = wsum[tid];
#pragma unroll
        for (int o = 16; o > 0; o >>= 1) w += __shfl_down_sync(~0u, w, o);
        if (tid == 0) g_bsum[blockIdx.x] = w;
    }
    if (tid < Gg && hist[tid]) atomicAdd(&g_gcnt[tid], (float)hist[tid]);
}

// ---------------- scan phase 2: scan the 49 block sums ------------------------
__global__ void k_scan2() {
    if (threadIdx.x == 0) {
        int run = 0;
        for (int b = 0; b < NSB; b++) { int t = g_bsum[b]; g_bsum[b] = run; run += t; }
        g_off[Nn] = run;
    }
}

// ---------------- scan phase 3: intra-block exclusive scan + outputs ----------
__global__ void k_scan3() {
    __shared__ int woff[32];
    int tid = threadIdx.x;
    int i = blockIdx.x * 1024 + tid;
    int d = (i < Nn) ? g_deg[i] + 1 : 0;
    int x = d;
#pragma unroll
    for (int o = 1; o < 32; o <<= 1) {
        int y = __shfl_up_sync(~0u, x, o);
        if ((tid & 31) >= o) x += y;
    }
    if ((tid & 31) == 31) woff[tid >> 5] = x;
    __syncthreads();
    if (tid < 32) {
        int w = woff[tid];
#pragma unroll
        for (int o = 1; o < 32; o <<= 1) {
            int y = __shfl_up_sync(~0u, w, o);
            if (tid >= o) w += y;
        }
        woff[tid] = w;
    }
    __syncthreads();
    int base = g_bsum[blockIdx.x] + ((tid >= 32) ? woff[(tid >> 5) - 1] : 0);
    int excl = base + x - d;
    if (i < Nn) {
        g_off[i] = excl;
        g_cur[i] = excl;
        g_dinv[i] = rsqrtf((float)d);
    }
}

// ---------------- fill CSC: combined (row, norm) AoS record -------------------
__global__ void k_fill(const int* __restrict__ row, const int* __restrict__ col) {
    int idx = blockIdx.x * blockDim.x + threadIdx.x;
    if (idx >= ET) return;
    int r, c;
    if (idx < Ee) { r = row[idx]; c = col[idx]; }
    else          { r = c = idx - Ee; }
    int pos = atomicAdd(&g_cur[c], 1);
    int2 rec;
    rec.x = r;
    rec.y = __float_as_int(g_dinv[r] * g_dinv[c]);
    g_edge[pos] = rec;
}

// ---------------- KAN GEMM: warp-specialized, K-chunks of 128 ----------------
// CTA: 128 nodes x 128 outs, 384 threads. 8 consumer warps (64x32 each),
// 4 producer warps (trig A-fill + B cp.async). Double-buffered K=128 stages.
#define A_STRIDE 136
#define ROW_B    (A_STRIDE * 2)              // 272 bytes
#define TILE_B   (128 * ROW_B)               // 34816 bytes
#define STAGE_B  (3 * TILE_B)                // A + Bh + Bl = 104448
#define A_OFF(s)  ((s) * STAGE_B)
#define BH_OFF(s) ((s) * STAGE_B + TILE_B)
#define BL_OFF(s) ((s) * STAGE_B + 2 * TILE_B)
#define SMEM_SZ  (2 * STAGE_B)               // 208896

template <int NCHUNK, typename OutT>
__global__ __launch_bounds__(NTHREADS, 1) void k_kan_mma(const float* __restrict__ X,
                                                         const __half* __restrict__ Wh,
                                                         const __half* __restrict__ Wl,
                                                         OutT* __restrict__ Y, int B) {
    extern __shared__ char sm[];
    const int INP = NCHUNK * 8;
    uint32_t sb = smem_u32(sm);
    int tid = threadIdx.x;
    int lane = tid & 31;
    int wid = tid >> 5;
    int nb = blockIdx.x * 128;

    if (wid < 8) {
        // ====== CONSUMER: 64 m-rows x 32 n-cols per warp, MMA only ======
        int m0 = (wid & 1) * 64;
        int n0 = (wid >> 1) * 32;
        int koff = (wid >> 2) * 4;          // de-phase warp halves per SMSP

        float d[4][4][4];
#pragma unroll
        for (int a = 0; a < 4; a++)
#pragma unroll
            for (int b = 0; b < 4; b++)
#pragma unroll
                for (int q = 0; q < 4; q++) d[a][b][q] = 0.f;

        uint32_t arow = (uint32_t)(((lane >> 3) & 1) * 8 + (lane & 7));
        uint32_t brow = (uint32_t)((lane >> 4) * 8 + (lane & 7));

        uint32_t fa[2][4][4], fbh[2][2][4], fbl[2][2][4];

        auto load_frags = [&](int buf, int kk, int s) {
            int k0 = kk * 16;
            uint32_t acol = (uint32_t)(k0 + (lane >> 4) * 8);
#pragma unroll
            for (int mt = 0; mt < 4; mt++)
                ldsm4(fa[buf][mt],
                      sb + A_OFF(s) + (uint32_t)((m0 + mt * 16 + arow) * ROW_B) + acol * 2);
            uint32_t bcol = (uint32_t)(k0 + ((lane >> 3) & 1) * 8);
#pragma unroll
            for (int np = 0; np < 2; np++) {
                uint32_t off = (uint32_t)((n0 + np * 16 + brow) * ROW_B) + bcol * 2;
                ldsm4(fbh[buf][np], sb + BH_OFF(s) + off);
                ldsm4(fbl[buf][np], sb + BL_OFF(s) + off);
            }
        };

        for (int c = 0; c < NCHUNK; c++) {
            int s = c & 1;
            bar_sync(FULL_ID(s));           // wait stage s filled

            load_frags(0, koff, s);
#pragma unroll
            for (int j = 0; j < 8; j++) {
                int cur = j & 1;
                if (j < 7) load_frags(cur ^ 1, (koff + j + 1) & 7, s);
#pragma unroll
                for (int np = 0; np < 2; np++)
#pragma unroll
                    for (int mt = 0; mt < 4; mt++) {
                        mma_f16(d[mt][np * 2 + 0], fa[cur][mt], fbh[cur][np] + 0);
                        mma_f16(d[mt][np * 2 + 1], fa[cur][mt], fbh[cur][np] + 2);
                    }
#pragma unroll
                for (int np = 0; np < 2; np++)
#pragma unroll
                    for (int mt = 0; mt < 4; mt++) {
                        mma_f16(d[mt][np * 2 + 0], fa[cur][mt], fbl[cur][np] + 0);
                        mma_f16(d[mt][np * 2 + 1], fa[cur][mt], fbl[cur][np] + 2);
                    }
            }
            bar_arrive(EMPTY_ID(s));        // release stage s
        }

        // ---- epilogue (4 m-tiles x 4 n8-slabs)
#pragma unroll
        for (int mt = 0; mt < 4; mt++) {
#pragma unroll
            for (int nt = 0; nt < 4; nt++) {
                int row = nb + m0 + mt * 16 + (lane >> 2);
                int out = n0 + nt * 8 + (lane & 3) * 2;
                if constexpr (sizeof(OutT) == 2) {
                    if (row < B) {
                        *(__half2*)&Y[(size_t)row * HIDf + out] =
                            __floats2half2_rn(d[mt][nt][0], d[mt][nt][1]);
                    }
                    if (row + 8 < B) {
                        *(__half2*)&Y[(size_t)(row + 8) * HIDf + out] =
                            __floats2half2_rn(d[mt][nt][2], d[mt][nt][3]);
                    }
                } else {
                    if (row < B) {
                        float2 p; p.x = d[mt][nt][0]; p.y = d[mt][nt][1];
                        *(float2*)&Y[(size_t)row * HIDf + out] = p;
                    }
                    if (row + 8 < B) {
                        float2 p; p.x = d[mt][nt][2]; p.y = d[mt][nt][3];
                        *(float2*)&Y[(size_t)(row + 8) * HIDf + out] = p;
                    }
                }
            }
        }
    } else {
        // ================= PRODUCER: A trig fill + B cp.async =================
        int pt = tid - 256;                 // 0..127 (one node per thread)
        bool pvalid = (nb + pt) < B;
        const float* xrow = X + (size_t)(nb + pt) * INP;

        for (int c = 0; c < NCHUNK; c++) {
            int s = c & 1;
            if (c >= 2) bar_sync(EMPTY_ID(s));   // wait consumers freed stage

            // ---- B: cp.async hi + lo K=128 chunks into stage s
            {
                const char* srcH = (const char*)(Wh + (size_t)c * CHUNK_ELEMS);
                const char* srcL = (const char*)(Wl + (size_t)c * CHUNK_ELEMS);
#pragma unroll
                for (int j = 0; j < 16; j++) {
                    int idx = pt + 128 * j;
                    uint32_t dof = (uint32_t)((idx >> 4) * ROW_B + (idx & 15) * 16);
                    cp16(sb + BH_OFF(s) + dof, srcH + idx * 16);
                    cp16(sb + BL_OFF(s) + dof, srcL + idx * 16);
                }
                cp_commit();
            }

            // ---- A: trig features for inputs 8c..8c+7 of node pt
            {
                float xs[8];
                if (pvalid) {
                    float4 a = *(const float4*)(xrow + 8 * c);
                    float4 b = *(const float4*)(xrow + 8 * c + 4);
                    xs[0] = a.x; xs[1] = a.y; xs[2] = a.z; xs[3] = a.w;
                    xs[4] = b.x; xs[5] = b.y; xs[6] = b.z; xs[7] = b.w;
                } else {
#pragma unroll
                    for (int j = 0; j < 8; j++) xs[j] = 0.f;
                }
#pragma unroll
                for (int j = 0; j < 8; j++) {
                    float s1, c1;
                    __sincosf(xs[j], &s1, &c1);
                    float cv[8], sv[8];
                    cv[0] = c1; sv[0] = s1;
#pragma unroll
                    for (int h = 1; h < 8; h++) {
                        cv[h] = cv[h - 1] * c1 - sv[h - 1] * s1;
                        sv[h] = sv[h - 1] * c1 + cv[h - 1] * s1;
                    }
                    float v[16];
#pragma unroll
                    for (int h = 0; h < 8; h++) { v[h] = cv[h]; v[8 + h] = sv[h]; }
                    uint32_t base = (uint32_t)(pt * ROW_B + j * 32);
#pragma unroll
                    for (int q = 0; q < 8; q++) {
                        *(__half2*)(sm + A_OFF(s) + base + q * 4) =
                            __floats2half2_rn(v[2 * q], v[2 * q + 1]);
                    }
                }
            }

            cp_wait<0>();          // B for this chunk landed
            membar_cta();          // STS + cp.async visible CTA-wide
            bar_arrive(FULL_ID(s));
        }
    }
}

// ---------------- aggregation: warp per dest node, AoS edges, fp16 gather ----
__global__ void k_aggregate(const __half* __restrict__ hin, float* __restrict__ hout) {
    int warp = (blockIdx.x * blockDim.x + threadIdx.x) >> 5;
    int lane = threadIdx.x & 31;
    if (warp >= Nn) return;
    int s = g_off[warp];
    int e = g_off[warp + 1];
    float ax = 0.f, ay = 0.f, az = 0.f, aw = 0.f;
    int k = s;
    for (; k + 1 < e; k += 2) {
        int2 e0 = g_edge[k];
        int2 e1 = g_edge[k + 1];
        float n0 = __int_as_float(e0.y);
        float n1 = __int_as_float(e1.y);
        const __half2* p0 = (const __half2*)(hin + (size_t)e0.x * HIDf + lane * 4);
        const __half2* p1 = (const __half2*)(hin + (size_t)e1.x * HIDf + lane * 4);
        float2 a0 = __half22float2(p0[0]), b0 = __half22float2(p0[1]);
        float2 a1 = __half22float2(p1[0]), b1 = __half22float2(p1[1]);
        ax += n0 * a0.x + n1 * a1.x;
        ay += n0 * a0.y + n1 * a1.y;
        az += n0 * b0.x + n1 * b1.x;
        aw += n0 * b0.y + n1 * b1.y;
    }
    if (k < e) {
        int2 e0 = g_edge[k];
        float n0 = __int_as_float(e0.y);
        const __half2* p0 = (const __half2*)(hin + (size_t)e0.x * HIDf + lane * 4);
        float2 a0 = __half22float2(p0[0]), b0 = __half22float2(p0[1]);
        ax += n0 * a0.x; ay += n0 * a0.y; az += n0 * b0.x; aw += n0 * b0.y;
    }
    float4 o; o.x = ax; o.y = ay; o.z = az; o.w = aw;
    *(float4*)&hout[(size_t)warp * HIDf + lane * 4] = o;
}

// ---------------- pooling: segmented (batch sorted) ---------------------------
#define PNODES 32
__global__ void k_pool(const float* __restrict__ h, const int* __restrict__ batch) {
    __shared__ int sbatch[PNODES];
    int f = threadIdx.x;             // feature 0..127
    int n0 = blockIdx.x * PNODES;
    if (f < PNODES) {
        int n = n0 + f;
        sbatch[f] = (n < Nn) ? batch[n] : -1;
    }
    __syncthreads();
    float acc = 0.f;
    int curb = sbatch[0];
#pragma unroll 4
    for (int j = 0; j < PNODES; j++) {
        int n = n0 + j;
        if (n >= Nn) break;
        int b = sbatch[j];
        if (b != curb) {
            atomicAdd(&g_pool[curb * HIDf + f], acc);
            acc = 0.f; curb = b;
        }
        acc += h[(size_t)n * HIDf + f];
    }
    if (curb >= 0) atomicAdd(&g_pool[curb * HIDf + f], acc);
}

// ---------------- readout KAN: [G=64, 128] -> [G, 32] (mean-div inline) -------
__global__ void k_readout(const float* __restrict__ Wread, float* __restrict__ out) {
    __shared__ float trig[HIDf * 16];
    int g = blockIdx.x;
    int tid = threadIdx.x;
    {
        float cnt = fmaxf(g_gcnt[g], 1.f);
        float x = g_pool[g * HIDf + tid] / cnt;
        float s1, c1;
        __sincosf(x, &s1, &c1);
        float c = c1, s = s1;
#pragma unroll
        for (int h = 0; h < Hh; h++) {
            trig[tid * 16 + h] = c;
            trig[tid * 16 + 8 + h] = s;
            float c2 = c * c1 - s * s1;
            s = s * c1 + c * s1;
            c = c2;
        }
    }
    __syncthreads();
    if (tid < LATf) {
        int o = tid;
        float acc = 0.f;
        for (int i = 0; i < HIDf; i++) {
#pragma unroll
            for (int h = 0; h < Hh; h++) {
                acc += trig[i * 16 + h]     * Wread[((0 * LATf + o) * HIDf + i) * Hh + h];
                acc += trig[i * 16 + 8 + h] * Wread[((1 * LATf + o) * HIDf + i) * Hh + h];
            }
        }
        out[g * LATf + o] = acc;
    }
}

// ---------------- launch ------------------------------------------------------
extern "C" void kernel_launch(void* const* d_in, const int* in_sizes, int n_in,
                              void* d_out, int out_size) {
    const float* feat  = (const float*)d_in[0];
    const int*   eidx  = (const int*)d_in[1];
    const int*   batch = (const int*)d_in[2];
    const float* We    = (const float*)d_in[3];
    const float* Wm    = (const float*)d_in[4];
    const float* Wread = (const float*)d_in[5];
    float* out = (float*)d_out;

    const int* row = eidx;
    const int* col = eidx + Ee;

    float *h0, *h1;
    __half *hk, *weh, *wel, *wmh, *wml;
    cudaGetSymbolAddress((void**)&h0,  g_h0);
    cudaGetSymbolAddress((void**)&h1,  g_h1);
    cudaGetSymbolAddress((void**)&hk,  g_hk);
    cudaGetSymbolAddress((void**)&weh, g_WEh);
    cudaGetSymbolAddress((void**)&wel, g_WEl);
    cudaGetSymbolAddress((void**)&wmh, g_WMh);
    cudaGetSymbolAddress((void**)&wml, g_WMl);

    cudaFuncSetAttribute(k_kan_mma<NCH_E, float>,
                         cudaFuncAttributeMaxDynamicSharedMemorySize, SMEM_SZ);
    cudaFuncSetAttribute(k_kan_mma<NCH_M, __half>,
                         cudaFuncAttributeMaxDynamicSharedMemorySize, SMEM_SZ);

    const int NTILE = (Nn + 127) / 128;   // 391

    // reorg (+ zero-init of deg/pool/gcnt fused in), degree count, scan phase 1
    k_reorg<<<(EMB_ELEMS + Ll * MP_ELEMS + 255) / 256, 256>>>(We, Wm);
    k_count<<<(Ee + 255) / 256, 256>>>(col);
    k_scan1<<<NSB, 1024>>>(batch);

    // embed (fp32 output: consumed directly as next kan input)
    k_kan_mma<NCH_E, float><<<NTILE, NTHREADS, SMEM_SZ>>>(feat, weh, wel, h0, Nn);

    // finish graph structure (scan phases 2-3, AoS edge fill)
    k_scan2<<<1, 32>>>();
    k_scan3<<<NSB, 1024>>>();
    k_fill<<<(ET + 255) / 256, 256>>>(row, col);

    // message passing layers (fp16 intermediate, fp32 aggregate output)
    const float* cur = h0;
    float* ping[2] = { h1, h0 };
    for (int l = 0; l < Ll; l++) {
        k_kan_mma<NCH_M, __half><<<NTILE, NTHREADS, SMEM_SZ>>>(
            cur, wmh + (size_t)l * NCH_M * CHUNK_ELEMS,
            wml + (size_t)l * NCH_M * CHUNK_ELEMS, hk, Nn);
        float* dst = ping[l & 1];
        k_aggregate<<<(Nn * 32 + 255) / 256, 256>>>(hk, dst);
        cur = dst;
    }

    // pool + readout (mean divide fused into readout)
    k_pool<<<(Nn + PNODES - 1) / PNODES, HIDf>>>(cur, batch);
    k_readout<<<Gg, HIDf>>>(Wread, out);
}